// round 6
// baseline (speedup 1.0000x reference)
#include <cuda_runtime.h>
#include <cstdint>

// CSPN propagation:
//   out[b,0,y,x] = sum_{t=0..24} gw[b,t,y+2,x+2] * src_t(y+2-t/5, x+2-t%5)
// src_t = h0 for t==12 (center) else hn; zero outside [0,H)x[0,W).
// All 25 taps read weight row (y+2) of their plane -> stage whole rows via cp.async.
// gw (4,25,356,1220) f32, hn/h0 (4,1,352,1216) f32, out (4,1,352,1216) f32.

#define K 5
#define Hc 352
#define Wc 1216
#define Hp 356
#define Wp 1220
#define Bc 4
#define NT 320                       // threads per block (304 compute, all copy)
#define F4_PER_TAP (Wp / 4)          // 305 float4 per tap row
#define F4_PER_STAGE (5 * F4_PER_TAP)// 1525 float4 per 5-tap stage

__device__ __forceinline__ uint32_t smem_u32(const void* p) {
    uint32_t a;
    asm("{.reg .u64 t; cvta.to.shared.u64 t, %1; cvt.u32.u64 %0, t;}"
        : "=r"(a) : "l"(p));
    return a;
}

__global__ __launch_bounds__(NT)
void cspn_kernel(const float* __restrict__ gw,
                 const float* __restrict__ hn,
                 const float* __restrict__ h0,
                 float* __restrict__ out)
{
    // 2-stage ring: 2 x 5 taps x 1220 floats = 48800 B (< 48KB static limit)
    __shared__ float wbuf[2][5][Wp];

    const int tid = threadIdx.x;
    const int row = blockIdx.x;              // 0..1407 = (b, y)
    const int y = row % Hc;
    const int b = row / Hc;

    const size_t PLANE = (size_t)Hp * Wp;    // 434320
    const float* wrow = gw + (size_t)b * 25 * PLANE + (size_t)(y + 2) * Wp;
    const float* hb   = hn + (size_t)b * Hc * Wc;
    const float* h0b  = h0 + (size_t)b * Hc * Wc;

    // ---- producer: stage s (taps 5s..5s+4, full 1220-wide aligned rows) ----
    auto issue_stage = [&](int s) {
        const float* src0 = wrow + (size_t)(s * 5) * PLANE;
        uint32_t dst0 = smem_u32(&wbuf[s & 1][0][0]);
        #pragma unroll 1
        for (int e = tid; e < F4_PER_STAGE; e += NT) {
            const int c = e / F4_PER_TAP;         // tap within stage
            const int j = e - c * F4_PER_TAP;     // float4 index in row
            const float* src = src0 + (size_t)c * PLANE + 4 * j;
            uint32_t dst = dst0 + (uint32_t)((c * Wp + 4 * j) * 4);
            asm volatile("cp.async.cg.shared.global [%0], [%1], 16;"
                         :: "r"(dst), "l"(src));
        }
    };

    issue_stage(0);
    asm volatile("cp.async.commit_group;");

    const int x = tid * 4;
    const bool active = (tid < Wc / 4);      // 304 compute threads

    float acc0 = 0.f, acc1 = 0.f, acc2 = 0.f, acc3 = 0.f;
    float4 c4 = make_float4(0.f, 0.f, 0.f, 0.f);
    if (active)
        c4 = *reinterpret_cast<const float4*>(h0b + (size_t)y * Wc + x);

    #pragma unroll
    for (int s = 0; s < 5; ++s) {            // stage s == tap row dy
        if (s + 1 < 5) issue_stage(s + 1);
        asm volatile("cp.async.commit_group;");   // empty group when s==4: keeps count uniform

        // hn span [x-2, x+5] for dy=s (register-resident, L1/L2-served)
        float v[8];
        {
            const int iy = y + 2 - s;
            const bool yok = (unsigned)iy < (unsigned)Hc;
            const float* rp = hb + (size_t)iy * Wc;
            #pragma unroll
            for (int k = 0; k < 8; ++k) {
                const int ix = x - 2 + k;
                v[k] = (active && yok && (unsigned)ix < (unsigned)Wc)
                         ? __ldg(rp + ix) : 0.f;
            }
        }

        asm volatile("cp.async.wait_group 1;");   // stage s resident
        __syncthreads();

        if (active) {
            const float* wst = &wbuf[s & 1][0][0];
            #pragma unroll
            for (int c = 0; c < 5; ++c) {
                const float* wp = wst + c * Wp + 2 + x;   // 8B-aligned
                const float2 wA = *reinterpret_cast<const float2*>(wp);
                const float2 wB = *reinterpret_cast<const float2*>(wp + 2);
                float s0, s1, s2, s3;
                if (s == 2 && c == 2) {                   // center tap t=12 -> h0
                    s0 = c4.x; s1 = c4.y; s2 = c4.z; s3 = c4.w;
                } else {
                    const int base = 4 - c;
                    s0 = v[base + 0]; s1 = v[base + 1];
                    s2 = v[base + 2]; s3 = v[base + 3];
                }
                acc0 = fmaf(wA.x, s0, acc0);
                acc1 = fmaf(wA.y, s1, acc1);
                acc2 = fmaf(wB.x, s2, acc2);
                acc3 = fmaf(wB.y, s3, acc3);
            }
        }
        __syncthreads();   // protect ring buffer before next issue overwrites it
    }

    if (active) {
        float4 o = make_float4(acc0, acc1, acc2, acc3);
        *reinterpret_cast<float4*>(out + (size_t)b * Hc * Wc + (size_t)y * Wc + x) = o;
    }
}

extern "C" void kernel_launch(void* const* d_in, const int* in_sizes, int n_in,
                              void* d_out, int out_size)
{
    const float* gw = (const float*)d_in[0];
    const float* hn = (const float*)d_in[1];
    const float* h0 = (const float*)d_in[2];
    float* out = (float*)d_out;

    cspn_kernel<<<Bc * Hc, NT>>>(gw, hn, h0, out);   // 1408 blocks
}